// round 2
// baseline (speedup 1.0000x reference)
#include <cuda_runtime.h>

// ---------------- problem dims ----------------
#define BEFF 1920        // effective batch (B*T/W)
#define HID 512
#define FDIM 25
#define ZDIM 256
#define GATES 2048       // 4*H
#define DECIN 537        // H + F
#define ROWS_PRED 96000  // B*T
#define C3D 58
#define NSTEP 50

// output layout (flattened tuple: prediction, coeff_3dmm, mu, logvar)
#define PRED_ELEMS  (128*750*25)        // 2400000
#define COEFF_ELEMS (128*750*58)        // 5568000
#define MU_ELEMS    (BEFF*ZDIM)         // 491520

// ---------------- scratch (__device__ globals; no allocation allowed) ------
__device__ float g_h[BEFF*HID];
__device__ float g_c[BEFF*HID];
__device__ float g_gates[BEFF*GATES];
__device__ float g_decin[BEFF*DECIN];   // [h_y | y_prev]
__device__ float g_m1[BEFF*HID];
__device__ float g_m2[BEFF*HID];
__device__ float g_mid[ROWS_PRED*HID];  // tanh(pred @ cr1^T)

// ---------------- GEMM tiling ----------------
#define BM 128
#define BN 64
#define BK 16
#define TM 8
#define TN 4
// 256 threads: tx = tid%16 (n dir, 16*4=64 cols), ty = tid/16 (m dir, 16*8=128 rows)

__device__ __forceinline__ unsigned long long pack2(float x, float y) {
    unsigned long long r;
    asm("mov.b64 %0, {%1,%2};" : "=l"(r) : "f"(x), "f"(y));
    return r;
}
__device__ __forceinline__ void fma2(unsigned long long& acc, unsigned long long a, unsigned long long b) {
    asm("fma.rn.f32x2 %0, %1, %2, %0;" : "+l"(acc) : "l"(a), "l"(b));
}

// C[m][n] = act( sum_k A1[m][k]*B1[n][k] + sum_k A2[m][k]*B2[n][k] + bias1[n] + bias2[n] )
// M is implied by gridDim.y * BM and is always a multiple of BM here.
// N is bounds-checked. K is arbitrary (zero-padded tiles).
__global__ __launch_bounds__(256) void gemm_2part(
    const float* __restrict__ A1, int lda1, int K1,
    const float* __restrict__ B1, int ldb1,
    const float* __restrict__ A2, int lda2, int K2,
    const float* __restrict__ B2, int ldb2,
    const float* __restrict__ bias1, const float* __restrict__ bias2,
    float* __restrict__ C, int ldc,
    float* __restrict__ C2, int ldc2,
    int N, int act)
{
    __shared__ float As[BK][BM + 4];
    __shared__ float Bs[BK][BN + 4];

    const int m0 = blockIdx.y * BM;
    const int n0 = blockIdx.x * BN;
    const int tid = threadIdx.x;
    const int tx = tid & 15;
    const int ty = tid >> 4;

    unsigned long long acc2[TM/2][TN];
#pragma unroll
    for (int i = 0; i < TM/2; i++)
#pragma unroll
        for (int j = 0; j < TN; j++) acc2[i][j] = 0ull;

    for (int part = 0; part < 2; part++) {
        const float* A = part ? A2 : A1;
        const float* B = part ? B2 : B1;
        const int lda = part ? lda2 : lda1;
        const int ldb = part ? ldb2 : ldb1;
        const int K   = part ? K2  : K1;
        if (A == nullptr || K == 0) continue;

        for (int k0 = 0; k0 < K; k0 += BK) {
            // A tile: BM x BK = 2048 elems, 8 per thread. consecutive tid -> consecutive kk (coalesced)
#pragma unroll
            for (int i = 0; i < 8; i++) {
                int idx = tid + i * 256;
                int r  = idx >> 4;      // 0..127
                int kk = idx & 15;
                float v = 0.f;
                if (k0 + kk < K) v = A[(size_t)(m0 + r) * lda + (k0 + kk)];
                As[kk][r] = v;
            }
            // B tile: BN x BK = 1024 elems, 4 per thread
#pragma unroll
            for (int i = 0; i < 4; i++) {
                int idx = tid + i * 256;
                int r  = idx >> 4;      // 0..63
                int kk = idx & 15;
                float v = 0.f;
                if ((n0 + r) < N && (k0 + kk) < K) v = B[(size_t)(n0 + r) * ldb + (k0 + kk)];
                Bs[kk][r] = v;
            }
            __syncthreads();

#pragma unroll
            for (int kk = 0; kk < BK; kk++) {
                float4 aLo = *(const float4*)&As[kk][ty * TM];
                float4 aHi = *(const float4*)&As[kk][ty * TM + 4];
                float4 bb  = *(const float4*)&Bs[kk][tx * TN];
                unsigned long long a2[4];
                a2[0] = pack2(aLo.x, aLo.y);
                a2[1] = pack2(aLo.z, aLo.w);
                a2[2] = pack2(aHi.x, aHi.y);
                a2[3] = pack2(aHi.z, aHi.w);
                unsigned long long b2[4];
                b2[0] = pack2(bb.x, bb.x);
                b2[1] = pack2(bb.y, bb.y);
                b2[2] = pack2(bb.z, bb.z);
                b2[3] = pack2(bb.w, bb.w);
#pragma unroll
                for (int i = 0; i < 4; i++)
#pragma unroll
                    for (int j = 0; j < 4; j++)
                        fma2(acc2[i][j], a2[i], b2[j]);
            }
            __syncthreads();
        }
    }

    // epilogue
#pragma unroll
    for (int j = 0; j < TN; j++) {
        int n = n0 + tx * TN + j;
        if (n >= N) continue;
        float bv = 0.f;
        if (bias1) bv += bias1[n];
        if (bias2) bv += bias2[n];
#pragma unroll
        for (int i = 0; i < TM/2; i++) {
            int m = m0 + ty * TM + 2 * i;
            float lo = __uint_as_float((unsigned)(acc2[i][j] & 0xffffffffull)) + bv;
            float hi = __uint_as_float((unsigned)(acc2[i][j] >> 32)) + bv;
            if (act == 1) { lo = tanhf(lo); hi = tanhf(hi); }
            C[(size_t)m * ldc + n] = lo;
            C[(size_t)(m + 1) * ldc + n] = hi;
            if (C2) {
                C2[(size_t)m * ldc2 + n] = lo;
                C2[(size_t)(m + 1) * ldc2 + n] = hi;
            }
        }
    }
}

// ---------------- LSTM pointwise ----------------
__device__ __forceinline__ float sigmoidf_(float x) { return 1.f / (1.f + expf(-x)); }

__global__ void lstm_pointwise(const float* __restrict__ gates,
                               float* __restrict__ h, float* __restrict__ c)
{
    int idx = blockIdx.x * blockDim.x + threadIdx.x;
    if (idx >= BEFF * HID) return;
    int n = idx >> 9;       // / 512
    int j = idx & 511;
    const float* g = gates + (size_t)n * GATES;
    float ig = g[j];
    float fg = g[j + 512];
    float gg = g[j + 1024];
    float og = g[j + 1536];
    float cn = sigmoidf_(fg) * c[idx] + sigmoidf_(ig) * tanhf(gg);
    c[idx] = cn;
    h[idx] = sigmoidf_(og) * tanhf(cn);
}

// ---------------- utility kernels ----------------
__global__ void zero_kernel(float* p, int n) {
    int i = blockIdx.x * blockDim.x + threadIdx.x;
    if (i < n) p[i] = 0.f;
}

__global__ void zero_yprev_kernel(float* decin) {   // zero g_decin[:, 512:537]
    int i = blockIdx.x * blockDim.x + threadIdx.x;
    if (i < BEFF * FDIM) {
        int n = i / FDIM, f = i % FDIM;
        decin[(size_t)n * DECIN + HID + f] = 0.f;
    }
}

// ---------------- launch ----------------
extern "C" void kernel_launch(void* const* d_in, const int* in_sizes, int n_in,
                              void* d_out, int out_size)
{
    (void)in_sizes; (void)n_in; (void)out_size;
    const float* emo     = (const float*)d_in[0];
    // d_in[1] = listener_3dmm (unused by the reference)
    const float* enc_Wih = (const float*)d_in[2];
    const float* enc_Whh = (const float*)d_in[3];
    const float* enc_bih = (const float*)d_in[4];
    const float* enc_bhh = (const float*)d_in[5];
    const float* mu_W    = (const float*)d_in[6];
    const float* mu_b    = (const float*)d_in[7];
    const float* lv_W    = (const float*)d_in[8];
    const float* lv_b    = (const float*)d_in[9];
    const float* zdec_W  = (const float*)d_in[10];
    const float* zdec_b  = (const float*)d_in[11];
    const float* dec_Wih = (const float*)d_in[12];
    const float* dec_Whh = (const float*)d_in[13];
    const float* dec_bih = (const float*)d_in[14];
    const float* dec_bhh = (const float*)d_in[15];
    const float* mlp1_W  = (const float*)d_in[16];
    const float* mlp1_b  = (const float*)d_in[17];
    const float* mlp2_W  = (const float*)d_in[18];
    const float* mlp2_b  = (const float*)d_in[19];
    const float* out_W   = (const float*)d_in[20];
    const float* out_b   = (const float*)d_in[21];
    const float* cr1_W   = (const float*)d_in[22];
    const float* cr1_b   = (const float*)d_in[23];
    const float* cr2_W   = (const float*)d_in[24];
    const float* cr2_b   = (const float*)d_in[25];

    float* out   = (float*)d_out;
    float* pred  = out;                                // 2,400,000
    float* coeff = out + PRED_ELEMS;                   // 5,568,000
    float* muO   = out + PRED_ELEMS + COEFF_ELEMS;     //   491,520
    float* lvO   = muO + MU_ELEMS;                     //   491,520

    float *hP, *cP, *gatesP, *decinP, *m1P, *m2P, *midP;
    cudaGetSymbolAddress((void**)&hP, g_h);
    cudaGetSymbolAddress((void**)&cP, g_c);
    cudaGetSymbolAddress((void**)&gatesP, g_gates);
    cudaGetSymbolAddress((void**)&decinP, g_decin);
    cudaGetSymbolAddress((void**)&m1P, g_m1);
    cudaGetSymbolAddress((void**)&m2P, g_m2);
    cudaGetSymbolAddress((void**)&midP, g_mid);

    const dim3 blk(256);
    const dim3 gGate(GATES / BN, BEFF / BM);   // 32 x 15
    const dim3 gH(HID / BN, BEFF / BM);        //  8 x 15
    const dim3 gZ(ZDIM / BN, BEFF / BM);       //  4 x 15
    const dim3 gY(1, BEFF / BM);               //  1 x 15
    const dim3 gC1(HID / BN, ROWS_PRED / BM);  //  8 x 750
    const dim3 gC2(1, ROWS_PRED / BM);         //  1 x 750
    const int pwGrid = (BEFF * HID + 255) / 256;

    // ---- encoder ----
    zero_kernel<<<pwGrid, blk>>>(hP, BEFF * HID);
    zero_kernel<<<pwGrid, blk>>>(cP, BEFF * HID);
    for (int t = 0; t < NSTEP; t++) {
        // gates = x_t @ Wih^T + h @ Whh^T + bih + bhh
        gemm_2part<<<gGate, blk>>>(
            emo + t * FDIM, NSTEP * FDIM, FDIM, enc_Wih, FDIM,
            hP, HID, HID, enc_Whh, HID,
            enc_bih, enc_bhh,
            gatesP, GATES, nullptr, 0, GATES, 0);
        lstm_pointwise<<<pwGrid, blk>>>(gatesP, hP, cP);
    }

    // ---- latent ----
    gemm_2part<<<gZ, blk>>>(hP, HID, HID, mu_W, HID,
                            nullptr, 0, 0, nullptr, 0,
                            mu_b, nullptr, muO, ZDIM, nullptr, 0, ZDIM, 0);
    gemm_2part<<<gZ, blk>>>(hP, HID, HID, lv_W, HID,
                            nullptr, 0, 0, nullptr, 0,
                            lv_b, nullptr, lvO, ZDIM, nullptr, 0, ZDIM, 0);
    // h_y = mu @ zdec_W^T + zdec_b   -> written into decin[:, 0:512]
    gemm_2part<<<gH, blk>>>(muO, ZDIM, ZDIM, zdec_W, ZDIM,
                            nullptr, 0, 0, nullptr, 0,
                            zdec_b, nullptr, decinP, DECIN, nullptr, 0, HID, 0);

    // ---- decoder ----
    zero_kernel<<<pwGrid, blk>>>(hP, BEFF * HID);
    zero_kernel<<<pwGrid, blk>>>(cP, BEFF * HID);
    zero_yprev_kernel<<<(BEFF * FDIM + 255) / 256, blk>>>(decinP);
    for (int t = 0; t < NSTEP; t++) {
        // gates = [h_y | y_prev] @ dec_Wih^T + h @ dec_Whh^T + biases
        gemm_2part<<<gGate, blk>>>(
            decinP, DECIN, DECIN, dec_Wih, DECIN,
            hP, HID, HID, dec_Whh, HID,
            dec_bih, dec_bhh,
            gatesP, GATES, nullptr, 0, GATES, 0);
        lstm_pointwise<<<pwGrid, blk>>>(gatesP, hP, cP);
        // m1 = tanh(h @ mlp1_W^T + b)
        gemm_2part<<<gH, blk>>>(hP, HID, HID, mlp1_W, HID,
                                nullptr, 0, 0, nullptr, 0,
                                mlp1_b, nullptr, m1P, HID, nullptr, 0, HID, 1);
        // m2 = tanh(m1 @ mlp2_W^T + b)
        gemm_2part<<<gH, blk>>>(m1P, HID, HID, mlp2_W, HID,
                                nullptr, 0, 0, nullptr, 0,
                                mlp2_b, nullptr, m2P, HID, nullptr, 0, HID, 1);
        // y = m2 @ out_W^T + b  -> prediction slice (ldc=1250) AND decin y_prev (ldc=537)
        gemm_2part<<<gY, blk>>>(m2P, HID, HID, out_W, HID,
                                nullptr, 0, 0, nullptr, 0,
                                out_b, nullptr,
                                pred + t * FDIM, NSTEP * FDIM,
                                decinP + HID, DECIN, FDIM, 0);
    }

    // ---- 3dmm head ----
    // mid = tanh(pred @ cr1_W^T + b)
    gemm_2part<<<gC1, blk>>>(pred, FDIM, FDIM, cr1_W, FDIM,
                             nullptr, 0, 0, nullptr, 0,
                             cr1_b, nullptr, midP, HID, nullptr, 0, HID, 1);
    // coeff = mid @ cr2_W^T + b
    gemm_2part<<<gC2, blk>>>(midP, HID, HID, cr2_W, HID,
                             nullptr, 0, 0, nullptr, 0,
                             cr2_b, nullptr, coeff, C3D, nullptr, 0, C3D, 0);
}

// round 17
// speedup vs baseline: 1.8512x; 1.8512x over previous
#include <cuda_runtime.h>
#include <cuda_bf16.h>
#include <cstdint>

// ---------------- problem dims ----------------
#define BEFF 1920
#define HID 512
#define FDIM 25
#define ZDIM 256
#define GATES 2048
#define ROWS_PRED 96000
#define C3D 58
#define NSTEP 50

#define PRED_ELEMS  (128*750*25)
#define COEFF_ELEMS (128*750*58)
#define MU_ELEMS    (BEFF*ZDIM)

// ---------------- tiled-swizzled bf16 format (TS) ----------------
// blocks of 128 rows x 64 cols (16KB), SW128-swizzled, block (bm,kc) at
// elements ((bm*nkch)+kc)*8192.

// ---------------- scratch ----------------
__device__ __nv_bfloat16 ts_emo_hi[50*15*8192],  ts_emo_lo[50*15*8192];
__device__ __nv_bfloat16 ts_eWih_hi[16*1*8192],  ts_eWih_lo[16*1*8192];
__device__ __nv_bfloat16 ts_eWhh_hi[16*8*8192],  ts_eWhh_lo[16*8*8192];
__device__ __nv_bfloat16 ts_dWih_hi[16*9*8192],  ts_dWih_lo[16*9*8192];
__device__ __nv_bfloat16 ts_dWhh_hi[16*8*8192],  ts_dWhh_lo[16*8*8192];
__device__ __nv_bfloat16 ts_mlp1_hi[4*8*8192],   ts_mlp1_lo[4*8*8192];
__device__ __nv_bfloat16 ts_mlp2_hi[4*8*8192],   ts_mlp2_lo[4*8*8192];
__device__ __nv_bfloat16 ts_outW_hi[1*8*8192],   ts_outW_lo[1*8*8192];
__device__ __nv_bfloat16 ts_zdec_hi[4*4*8192],   ts_zdec_lo[4*4*8192];
__device__ __nv_bfloat16 ts_muW_hi[2*8*8192],    ts_muW_lo[2*8*8192];
__device__ __nv_bfloat16 ts_lvW_hi[2*8*8192],    ts_lvW_lo[2*8*8192];
__device__ __nv_bfloat16 ts_cr1_hi[4*1*8192],    ts_cr1_lo[4*1*8192];
__device__ __nv_bfloat16 ts_cr2_hi[1*8*8192],    ts_cr2_lo[1*8*8192];
// ping-pong h buffers (intra-kernel RAW race fix: gate GEMM reads h[t&1], writes h[(t+1)&1])
__device__ __nv_bfloat16 ts_hA_hi[15*8*8192],    ts_hA_lo[15*8*8192];
__device__ __nv_bfloat16 ts_hB_hi[15*8*8192],    ts_hB_lo[15*8*8192];
__device__ __nv_bfloat16 ts_decin_hi[15*9*8192], ts_decin_lo[15*9*8192];
__device__ __nv_bfloat16 ts_m1_hi[15*8*8192],    ts_m1_lo[15*8*8192];
__device__ __nv_bfloat16 ts_m2_hi[15*8*8192],    ts_m2_lo[15*8*8192];
__device__ __nv_bfloat16 ts_mu_hi[15*4*8192],    ts_mu_lo[15*4*8192];
__device__ __nv_bfloat16 ts_pred_hi[750*1*8192], ts_pred_lo[750*1*8192];
__device__ __nv_bfloat16 ts_mid_hi[750*8*8192],  ts_mid_lo[750*8*8192];
__device__ float g_c[BEFF*HID];

// ---------------- helpers ----------------
__device__ __forceinline__ uint32_t smem_u32(const void* p) {
    uint32_t a;
    asm("{ .reg .u64 t; cvta.to.shared.u64 t, %1; cvt.u32.u64 %0, t; }" : "=r"(a) : "l"(p));
    return a;
}
// swizzled byte offset within a 128x64 TS block
__device__ __forceinline__ uint32_t ts_inner(int r, int c) {
    uint32_t o = (((uint32_t)r & 127) << 7) | (((uint32_t)c & 63) << 1);
    return o ^ ((o >> 3) & 0x70);
}
__device__ __forceinline__ size_t ts_byteoff(int r, int col, int nkch) {
    return (((size_t)((r >> 7) * nkch + (col >> 6))) << 14) + ts_inner(r, col);
}
__device__ __forceinline__ void ts_store(__nv_bfloat16* hi, __nv_bfloat16* lo, int r, int col, int nkch, float v) {
    size_t off = ts_byteoff(r, col, nkch);
    __nv_bfloat16 h = __float2bfloat16(v);
    *(__nv_bfloat16*)((char*)hi + off) = h;
    *(__nv_bfloat16*)((char*)lo + off) = __float2bfloat16(v - __bfloat162float(h));
}

__device__ __forceinline__ void ldsm4(uint32_t* f, uint32_t addr) {
    asm volatile("ldmatrix.sync.aligned.m8n8.x4.shared.b16 {%0,%1,%2,%3}, [%4];"
        : "=r"(f[0]), "=r"(f[1]), "=r"(f[2]), "=r"(f[3]) : "r"(addr));
}
__device__ __forceinline__ void mma16816(float* d, const uint32_t* a, const uint32_t* b) {
    asm volatile("mma.sync.aligned.m16n8k16.row.col.f32.bf16.bf16.f32 "
        "{%0,%1,%2,%3}, {%4,%5,%6,%7}, {%8,%9}, {%0,%1,%2,%3};"
        : "+f"(d[0]), "+f"(d[1]), "+f"(d[2]), "+f"(d[3])
        : "r"(a[0]), "r"(a[1]), "r"(a[2]), "r"(a[3]), "r"(b[0]), "r"(b[1]));
}
#define CP16(dst, src) \
    asm volatile("cp.async.cg.shared.global [%0], [%1], 16;" :: "r"(dst), "l"(src) : "memory")

__device__ __forceinline__ float sigf(float x) { return 1.f / (1.f + expf(-x)); }

// ---------------- conversion kernels ----------------
// fp32 [N x K] row-major -> TS hi/lo. permute (gate weights): dst row p holds
// src row g*512+u with u=((p>>6)<<4)|(p&15), g=(p>>4)&3  (epilogue-fragment friendly)
__global__ void convW(const float* __restrict__ src, __nv_bfloat16* hi, __nv_bfloat16* lo,
                      int N, int K, int nkch, int total, int permute)
{
    int idx = blockIdx.x * blockDim.x + threadIdx.x;
    if (idx >= total) return;
    int cw = nkch << 6;
    int r = idx / cw, c = idx - r * cw;
    int sr = r;
    if (permute) {
        int u = ((r >> 6) << 4) | (r & 15);
        int g = (r >> 4) & 3;
        sr = g * 512 + u;
    }
    float v = (sr < N && c < K) ? src[(size_t)sr * K + c] : 0.f;
    size_t off = ts_byteoff(r, c, nkch);
    __nv_bfloat16 h = __float2bfloat16(v);
    *(__nv_bfloat16*)((char*)hi + off) = h;
    *(__nv_bfloat16*)((char*)lo + off) = __float2bfloat16(v - __bfloat162float(h));
}

// emo (B,T,F) -> 50 TS matrices of (1920 x 64pad), t-major
__global__ void convEmo(const float* __restrict__ emo, __nv_bfloat16* hi, __nv_bfloat16* lo)
{
    int idx = blockIdx.x * blockDim.x + threadIdx.x;
    if (idx >= 50 * 1920 * 64) return;
    int t = idx / (1920 * 64);
    int rem = idx - t * (1920 * 64);
    int n = rem >> 6, c = rem & 63;
    float v = (c < FDIM) ? emo[(size_t)n * 1250 + t * FDIM + c] : 0.f;
    size_t off = ((size_t)t * 15 * 8192) * 2 + ts_byteoff(n, c, 1);
    __nv_bfloat16 h = __float2bfloat16(v);
    *(__nv_bfloat16*)((char*)hi + off) = h;
    *(__nv_bfloat16*)((char*)lo + off) = __float2bfloat16(v - __bfloat162float(h));
}

__global__ void zero_bf2(__nv_bfloat16* a, __nv_bfloat16* b, int n) {
    int i = blockIdx.x * blockDim.x + threadIdx.x;
    if (i < n) { a[i] = __float2bfloat16(0.f); b[i] = __float2bfloat16(0.f); }
}
__global__ void zero_f32(float* p, int n) {
    int i = blockIdx.x * blockDim.x + threadIdx.x;
    if (i < n) p[i] = 0.f;
}

// ---------------- HMMA GEMM ----------------
// CTA 128x128 (8 warps, warp tile 32m x 64n), K in 64-wide TS chunks,
// bf16x3 split (AhBh + AhBl + AlBh), modes:
//   0: v (+bias) -> fp32 C [ldc] and/or TS dest (col offset ts_col0)
//   1: same + tanh
//   2: fused LSTM (gate-permuted weights): C = cell state [x512], TS dest = h_out
#define SM_AH 0
#define SM_AL 16384
#define SM_BH 32768
#define SM_BL 49152
#define SM_TOTAL 65536

__global__ __launch_bounds__(256, 2)
void hmma_gemm(const __nv_bfloat16* __restrict__ aHi1, const __nv_bfloat16* __restrict__ aLo1,
               const __nv_bfloat16* __restrict__ bHi1, const __nv_bfloat16* __restrict__ bLo1, int nk1,
               const __nv_bfloat16* __restrict__ aHi2, const __nv_bfloat16* __restrict__ aLo2,
               const __nv_bfloat16* __restrict__ bHi2, const __nv_bfloat16* __restrict__ bLo2, int nk2,
               const float* __restrict__ bias1, const float* __restrict__ bias2,
               float* __restrict__ C, int ldc,
               __nv_bfloat16* __restrict__ tsHi, __nv_bfloat16* __restrict__ tsLo, int ts_nkch, int ts_col0,
               int Nreal, int mode)
{
    extern __shared__ char smem[];
    const uint32_t sb = smem_u32(smem);
    const int tid = threadIdx.x;
    const int lane = tid & 31, warp = tid >> 5;
    const int wm = warp & 3, wn = warp >> 2;          // 4 x 2 warp grid
    const int grp = lane >> 2, tig = lane & 3;
    const int m0 = blockIdx.y << 7, n0 = blockIdx.x << 7;

    float acc[2][8][4];
#pragma unroll
    for (int mi = 0; mi < 2; mi++)
#pragma unroll
        for (int j = 0; j < 8; j++)
#pragma unroll
            for (int q = 0; q < 4; q++) acc[mi][j][q] = 0.f;

    // ldmatrix lane-address components
    const int rA_l = (lane & 7) + ((lane >> 3) & 1) * 8;   // + mi*16 + wm*32
    const int cA_l = ((lane >> 4) & 1) * 8;                // + ks*16
    const int rB_l = (lane & 7) + ((lane >> 4) & 1) * 8;   // + jp*16 + wn*64
    const int cB_l = ((lane >> 3) & 1) * 8;                // + ks*16

    for (int part = 0; part < 2; part++) {
        const __nv_bfloat16* pah = part ? aHi2 : aHi1;
        const __nv_bfloat16* pal = part ? aLo2 : aLo1;
        const __nv_bfloat16* pbh = part ? bHi2 : bHi1;
        const __nv_bfloat16* pbl = part ? bLo2 : bLo1;
        const int nk = part ? nk2 : nk1;
        if (pbh == nullptr) continue;

        for (int kc = 0; kc < nk; kc++) {
            const char* gAH = (const char*)pah + (((size_t)(blockIdx.y * nk + kc)) << 14);
            const char* gAL = (const char*)pal + (((size_t)(blockIdx.y * nk + kc)) << 14);
            const char* gBH = (const char*)pbh + (((size_t)(blockIdx.x * nk + kc)) << 14);
            const char* gBL = (const char*)pbl + (((size_t)(blockIdx.x * nk + kc)) << 14);
#pragma unroll
            for (int i = 0; i < 4; i++) {
                int o = (tid + (i << 8)) << 4;
                CP16(sb + SM_AH + o, gAH + o);
                CP16(sb + SM_AL + o, gAL + o);
                CP16(sb + SM_BH + o, gBH + o);
                CP16(sb + SM_BL + o, gBL + o);
            }
            asm volatile("cp.async.commit_group;" ::: "memory");
            asm volatile("cp.async.wait_group 0;" ::: "memory");
            __syncthreads();

#pragma unroll
            for (int pass = 0; pass < 3; pass++) {
                const uint32_t aBase = sb + (pass == 2 ? SM_AL : SM_AH);
                const uint32_t bBase = sb + (pass == 1 ? SM_BL : SM_BH);
#pragma unroll
                for (int ks = 0; ks < 4; ks++) {
                    uint32_t af[2][4];
#pragma unroll
                    for (int mi = 0; mi < 2; mi++)
                        ldsm4(af[mi], aBase + ts_inner(wm * 32 + mi * 16 + rA_l, ks * 16 + cA_l));
                    uint32_t bf[8][2];
#pragma unroll
                    for (int jp = 0; jp < 4; jp++) {
                        uint32_t t4[4];
                        ldsm4(t4, bBase + ts_inner(wn * 64 + jp * 16 + rB_l, ks * 16 + cB_l));
                        bf[jp * 2][0] = t4[0]; bf[jp * 2][1] = t4[1];
                        bf[jp * 2 + 1][0] = t4[2]; bf[jp * 2 + 1][1] = t4[3];
                    }
#pragma unroll
                    for (int mi = 0; mi < 2; mi++)
#pragma unroll
                        for (int j = 0; j < 8; j++)
                            mma16816(acc[mi][j], af[mi], bf[j]);
                }
            }
            __syncthreads();
        }
    }

    // ---------------- epilogue ----------------
    if (mode == 2) {
        const int ubase = (n0 + wn * 64) >> 2;
#pragma unroll
        for (int jj = 0; jj < 2; jj++)
#pragma unroll
            for (int p = 0; p < 2; p++) {
                int u = ubase + 8 * jj + 2 * tig + p;
                float bi = bias1[u] + bias2[u];
                float bff = bias1[512 + u] + bias2[512 + u];
                float bg = bias1[1024 + u] + bias2[1024 + u];
                float bo = bias1[1536 + u] + bias2[1536 + u];
#pragma unroll
                for (int mi = 0; mi < 2; mi++)
#pragma unroll
                    for (int rr = 0; rr < 2; rr++) {
                        int q = rr * 2 + p;
                        int r = m0 + wm * 32 + mi * 16 + grp + rr * 8;
                        float iv = acc[mi][jj][q] + bi;
                        float fv = acc[mi][2 + jj][q] + bff;
                        float gv = acc[mi][4 + jj][q] + bg;
                        float ov = acc[mi][6 + jj][q] + bo;
                        size_t ci = (size_t)r * 512 + u;
                        float cn = sigf(fv) * C[ci] + sigf(iv) * tanhf(gv);
                        C[ci] = cn;
                        ts_store(tsHi, tsLo, r, u, ts_nkch, sigf(ov) * tanhf(cn));
                    }
            }
    } else {
#pragma unroll
        for (int mi = 0; mi < 2; mi++)
#pragma unroll
            for (int j = 0; j < 8; j++)
#pragma unroll
                for (int q = 0; q < 4; q++) {
                    int col = wn * 64 + j * 8 + 2 * tig + (q & 1);
                    int n = n0 + col;
                    if (n >= Nreal) continue;
                    int r = m0 + wm * 32 + mi * 16 + grp + (q >> 1) * 8;
                    float v = acc[mi][j][q];
                    if (bias1) v += bias1[n];
                    if (bias2) v += bias2[n];
                    if (mode == 1) v = tanhf(v);
                    if (C) C[(size_t)r * ldc + n] = v;
                    if (tsHi) ts_store(tsHi, tsLo, r, ts_col0 + n, ts_nkch, v);
                }
    }
}

// ---------------- host ----------------
#define SYM(p, s) cudaGetSymbolAddress((void**)&p, s)

extern "C" void kernel_launch(void* const* d_in, const int* in_sizes, int n_in,
                              void* d_out, int out_size)
{
    (void)in_sizes; (void)n_in; (void)out_size;
    const float* emo     = (const float*)d_in[0];
    const float* enc_Wih = (const float*)d_in[2];
    const float* enc_Whh = (const float*)d_in[3];
    const float* enc_bih = (const float*)d_in[4];
    const float* enc_bhh = (const float*)d_in[5];
    const float* mu_W    = (const float*)d_in[6];
    const float* mu_b    = (const float*)d_in[7];
    const float* lv_W    = (const float*)d_in[8];
    const float* lv_b    = (const float*)d_in[9];
    const float* zdec_W  = (const float*)d_in[10];
    const float* zdec_b  = (const float*)d_in[11];
    const float* dec_Wih = (const float*)d_in[12];
    const float* dec_Whh = (const float*)d_in[13];
    const float* dec_bih = (const float*)d_in[14];
    const float* dec_bhh = (const float*)d_in[15];
    const float* mlp1_W  = (const float*)d_in[16];
    const float* mlp1_b  = (const float*)d_in[17];
    const float* mlp2_W  = (const float*)d_in[18];
    const float* mlp2_b  = (const float*)d_in[19];
    const float* out_W   = (const float*)d_in[20];
    const float* out_b   = (const float*)d_in[21];
    const float* cr1_W   = (const float*)d_in[22];
    const float* cr1_b   = (const float*)d_in[23];
    const float* cr2_W   = (const float*)d_in[24];
    const float* cr2_b   = (const float*)d_in[25];

    float* out   = (float*)d_out;
    float* pred  = out;
    float* coeff = out + PRED_ELEMS;
    float* muO   = out + PRED_ELEMS + COEFF_ELEMS;
    float* lvO   = muO + MU_ELEMS;

    __nv_bfloat16 *emoH,*emoL,*eWihH,*eWihL,*eWhhH,*eWhhL,*dWihH,*dWihL,*dWhhH,*dWhhL;
    __nv_bfloat16 *mlp1H,*mlp1L,*mlp2H,*mlp2L,*outWH,*outWL,*zdecH,*zdecL,*muWH,*muWL,*lvWH,*lvWL;
    __nv_bfloat16 *cr1H,*cr1L,*cr2H,*cr2L,*dinH,*dinL,*m1H,*m1L,*m2H,*m2L,*muH,*muL,*prH,*prL,*midH,*midL;
    __nv_bfloat16 *hH[2], *hL[2];
    float* cP;
    SYM(emoH, ts_emo_hi);   SYM(emoL, ts_emo_lo);
    SYM(eWihH, ts_eWih_hi); SYM(eWihL, ts_eWih_lo);
    SYM(eWhhH, ts_eWhh_hi); SYM(eWhhL, ts_eWhh_lo);
    SYM(dWihH, ts_dWih_hi); SYM(dWihL, ts_dWih_lo);
    SYM(dWhhH, ts_dWhh_hi); SYM(dWhhL, ts_dWhh_lo);
    SYM(mlp1H, ts_mlp1_hi); SYM(mlp1L, ts_mlp1_lo);
    SYM(mlp2H, ts_mlp2_hi); SYM(mlp2L, ts_mlp2_lo);
    SYM(outWH, ts_outW_hi); SYM(outWL, ts_outW_lo);
    SYM(zdecH, ts_zdec_hi); SYM(zdecL, ts_zdec_lo);
    SYM(muWH, ts_muW_hi);   SYM(muWL, ts_muW_lo);
    SYM(lvWH, ts_lvW_hi);   SYM(lvWL, ts_lvW_lo);
    SYM(cr1H, ts_cr1_hi);   SYM(cr1L, ts_cr1_lo);
    SYM(cr2H, ts_cr2_hi);   SYM(cr2L, ts_cr2_lo);
    SYM(hH[0], ts_hA_hi);   SYM(hL[0], ts_hA_lo);
    SYM(hH[1], ts_hB_hi);   SYM(hL[1], ts_hB_lo);
    SYM(dinH, ts_decin_hi); SYM(dinL, ts_decin_lo);
    SYM(m1H, ts_m1_hi);     SYM(m1L, ts_m1_lo);
    SYM(m2H, ts_m2_hi);     SYM(m2L, ts_m2_lo);
    SYM(muH, ts_mu_hi);     SYM(muL, ts_mu_lo);
    SYM(prH, ts_pred_hi);   SYM(prL, ts_pred_lo);
    SYM(midH, ts_mid_hi);   SYM(midL, ts_mid_lo);
    SYM(cP, g_c);

    cudaFuncSetAttribute(hmma_gemm, cudaFuncAttributeMaxDynamicSharedMemorySize, SM_TOTAL);

    const dim3 blk(256);
#define CGRID(n) (((n) + 255) / 256)
    // ---- conversions ----
    convEmo<<<CGRID(50*1920*64), blk>>>(emo, emoH, emoL);
    convW<<<CGRID(16*128*64),  blk>>>(enc_Wih, eWihH, eWihL, 2048, 25, 1, 16*128*64, 1);
    convW<<<CGRID(16*128*512), blk>>>(enc_Whh, eWhhH, eWhhL, 2048, 512, 8, 16*128*512, 1);
    convW<<<CGRID(16*128*576), blk>>>(dec_Wih, dWihH, dWihL, 2048, 537, 9, 16*128*576, 1);
    convW<<<CGRID(16*128*512), blk>>>(dec_Whh, dWhhH, dWhhL, 2048, 512, 8, 16*128*512, 1);
    convW<<<CGRID(4*128*512),  blk>>>(mlp1_W, mlp1H, mlp1L, 512, 512, 8, 4*128*512, 0);
    convW<<<CGRID(4*128*512),  blk>>>(mlp2_W, mlp2H, mlp2L, 512, 512, 8, 4*128*512, 0);
    convW<<<CGRID(1*128*512),  blk>>>(out_W, outWH, outWL, 25, 512, 8, 1*128*512, 0);
    convW<<<CGRID(4*128*256),  blk>>>(zdec_W, zdecH, zdecL, 512, 256, 4, 4*128*256, 0);
    convW<<<CGRID(2*128*512),  blk>>>(mu_W, muWH, muWL, 256, 512, 8, 2*128*512, 0);
    convW<<<CGRID(2*128*512),  blk>>>(lv_W, lvWH, lvWL, 256, 512, 8, 2*128*512, 0);
    convW<<<CGRID(4*128*64),   blk>>>(cr1_W, cr1H, cr1L, 512, 25, 1, 4*128*64, 0);
    convW<<<CGRID(1*128*512),  blk>>>(cr2_W, cr2H, cr2L, 58, 512, 8, 1*128*512, 0);

    const dim3 gGate(16, 15), gH4(4, 15), gZ(2, 15), gY(1, 15), gC1(4, 750), gC2(1, 750), gHy(4, 15);

    // ---- encoder ----
    zero_bf2<<<CGRID(15*8*8192), blk>>>(hH[0], hL[0], 15*8*8192);
    zero_f32<<<CGRID(BEFF*HID), blk>>>(cP, BEFF*HID);
    for (int t = 0; t < NSTEP; t++) {
        int ri = t & 1, wi = ri ^ 1;
        hmma_gemm<<<gGate, blk, SM_TOTAL>>>(
            emoH + (size_t)t*15*8192, emoL + (size_t)t*15*8192, eWihH, eWihL, 1,
            hH[ri], hL[ri], eWhhH, eWhhL, 8,
            enc_bih, enc_bhh, cP, 512, hH[wi], hL[wi], 8, 0, 2048, 2);
    }
    // after 50 steps final h is in buffer 0
    // ---- latent ----
    hmma_gemm<<<gZ, blk, SM_TOTAL>>>(hH[0], hL[0], muWH, muWL, 8, nullptr,nullptr,nullptr,nullptr,0,
                                     mu_b, nullptr, muO, 256, muH, muL, 4, 0, 256, 0);
    hmma_gemm<<<gZ, blk, SM_TOTAL>>>(hH[0], hL[0], lvWH, lvWL, 8, nullptr,nullptr,nullptr,nullptr,0,
                                     lv_b, nullptr, lvO, 256, nullptr, nullptr, 0, 0, 256, 0);
    zero_bf2<<<CGRID(15*9*8192), blk>>>(dinH, dinL, 15*9*8192);
    hmma_gemm<<<gHy, blk, SM_TOTAL>>>(muH, muL, zdecH, zdecL, 4, nullptr,nullptr,nullptr,nullptr,0,
                                      zdec_b, nullptr, nullptr, 0, dinH, dinL, 9, 0, 512, 0);
    // ---- decoder ----
    zero_bf2<<<CGRID(15*8*8192), blk>>>(hH[0], hL[0], 15*8*8192);
    zero_f32<<<CGRID(BEFF*HID), blk>>>(cP, BEFF*HID);
    for (int t = 0; t < NSTEP; t++) {
        int ri = t & 1, wi = ri ^ 1;
        hmma_gemm<<<gGate, blk, SM_TOTAL>>>(
            dinH, dinL, dWihH, dWihL, 9,
            hH[ri], hL[ri], dWhhH, dWhhL, 8,
            dec_bih, dec_bhh, cP, 512, hH[wi], hL[wi], 8, 0, 2048, 2);
        hmma_gemm<<<gH4, blk, SM_TOTAL>>>(hH[wi], hL[wi], mlp1H, mlp1L, 8, nullptr,nullptr,nullptr,nullptr,0,
                                          mlp1_b, nullptr, nullptr, 0, m1H, m1L, 8, 0, 512, 1);
        hmma_gemm<<<gH4, blk, SM_TOTAL>>>(m1H, m1L, mlp2H, mlp2L, 8, nullptr,nullptr,nullptr,nullptr,0,
                                          mlp2_b, nullptr, nullptr, 0, m2H, m2L, 8, 0, 512, 1);
        hmma_gemm<<<gY, blk, SM_TOTAL>>>(m2H, m2L, outWH, outWL, 8, nullptr,nullptr,nullptr,nullptr,0,
                                         out_b, nullptr, pred + t*FDIM, 1250, dinH, dinL, 9, 512, 25, 0);
    }
    // ---- 3dmm head ----
    convW<<<CGRID(750*128*64), blk>>>(pred, prH, prL, 96000, 25, 1, 750*128*64, 0);
    hmma_gemm<<<gC1, blk, SM_TOTAL>>>(prH, prL, cr1H, cr1L, 1, nullptr,nullptr,nullptr,nullptr,0,
                                      cr1_b, nullptr, nullptr, 0, midH, midL, 8, 0, 512, 1);
    hmma_gemm<<<gC2, blk, SM_TOTAL>>>(midH, midL, cr2H, cr2L, 8, nullptr,nullptr,nullptr,nullptr,0,
                                      cr2_b, nullptr, coeff, 58, nullptr, nullptr, 0, 0, 58, 0);
}